// round 16
// baseline (speedup 1.0000x reference)
#include <cuda_runtime.h>
#include <cuda_fp16.h>
#include <cstdint>
#include <cfloat>

#define KC 120
#define DC 128
#define NMAX 262144
#define TILE_M 128
#define SROW 121          // S row stride (floats), odd => conflict-free
#define XST 72            // f16 row stride (64 + 8 pad) => conflict-free ldmatrix

typedef unsigned long long u64;

// ---------------- device scratch ----------------
__device__ float  g_cent[2][KC * DC];
__device__ float  g_csq[2][KC];
__device__ float  g_sums[KC * DC];
__device__ float  g_counts[KC];
__device__ int    g_labels[2][NMAX];
__device__ double g_acc[2];
// X and C in plain fp16 (X once per replay; C per iteration)
__device__ __half g_xh[2][NMAX * DC];
__device__ __half g_ch[2][KC * DC];

// single dynamic-smem symbol shared by all kernels (cast locally)
extern __shared__ char dyn_smem[];

// ---------------- smem layout (gemm kernel) ----------------
#define OFF_CSQ 0                       // 128 floats
#define OFF_RED 512                     // 8 floats
#define OFF_XH0 1024                    // 128 x 72 f16 = 18432 B
#define OFF_CH0 (1024 + 18432)
#define OFF_XH1 (1024 + 2 * 18432)
#define OFF_CH1 (1024 + 3 * 18432)
#define OFF_S   1024                    // epilogue S overlaps staging
#define GEMM_SMEM (1024 + 4 * 18432)    // 74752 B

// m16n8k16 f16 mma, fp32 accumulate
__device__ __forceinline__ void mma16816(float* c, const uint32_t* a,
                                         uint32_t b0, uint32_t b1) {
    asm volatile(
        "mma.sync.aligned.m16n8k16.row.col.f32.f16.f16.f32 "
        "{%0,%1,%2,%3}, {%4,%5,%6,%7}, {%8,%9}, {%0,%1,%2,%3};"
        : "+f"(c[0]), "+f"(c[1]), "+f"(c[2]), "+f"(c[3])
        : "r"(a[0]), "r"(a[1]), "r"(a[2]), "r"(a[3]), "r"(b0), "r"(b1));
}
__device__ __forceinline__ void ldsm_x4(uint32_t* r, uint32_t addr) {
    asm volatile("ldmatrix.sync.aligned.m8n8.x4.shared.b16 {%0,%1,%2,%3}, [%4];"
        : "=r"(r[0]), "=r"(r[1]), "=r"(r[2]), "=r"(r[3]) : "r"(addr));
}
#define CP_ASYNC16(dst, src) \
    asm volatile("cp.async.cg.shared.global [%0], [%1], 16;" :: "r"(dst), "l"(src))
#define CP_COMMIT() asm volatile("cp.async.commit_group;")
#define CP_WAIT(n)  asm volatile("cp.async.wait_group %0;" :: "n"(n))

// ================= one-time fp16 conversion of X =================
__global__ __launch_bounds__(256)
void preconvert_kernel(const float* __restrict__ x, int set, int total4) {
    int idx = blockIdx.x * 256 + threadIdx.x;    // float4 index
    if (idx >= total4) return;
    float4 v = ((const float4*)x)[idx];
    __half2* dh = (__half2*)(g_xh[set]) + idx * 2;
    dh[0] = __halves2half2(__float2half_rn(v.x), __float2half_rn(v.y));
    dh[1] = __halves2half2(__float2half_rn(v.z), __float2half_rn(v.w));
}

// ================= tensor-core GEMM + head (pure fp16, fp32 acc) =================
// dot[p][k] = x16_p (features xset) . c16_k (centroids cset).
// mode 0 (xset==cset): argmin_k (csq[k] - 2*dot) -> g_labels[cset]
// mode 1: CE_i = logsumexp(2.5*dot) - 2.5*dot[lab_i], lab from g_labels[cset] -> g_acc[aidx]
__global__ __launch_bounds__(256, 2)
void gemm_head_kernel(int xset, int cset, int mode, int aidx, int N) {
    char* sm = dyn_smem;
    float*  csq_s = (float*)(sm + OFF_CSQ);
    float*  S  = (float*)(sm + OFF_S);

    int tid = threadIdx.x;
    int lane = tid & 31, g = lane >> 2, t = lane & 3;
    int warp = tid >> 5;
    int wm = warp >> 1;            // 0..3  -> rows wm*32
    int wn = warp & 1;             // 0..1  -> cols wn*64
    int pm = wm * 32;
    int nb = wn * 64;

    if (mode == 0 && tid < KC) csq_s[tid] = g_csq[cset][tid];

    int tile0 = blockIdx.x * TILE_M;

    float acc[2][8][4];
    #pragma unroll
    for (int mi = 0; mi < 2; mi++)
        #pragma unroll
        for (int ni = 0; ni < 8; ni++)
            #pragma unroll
            for (int q = 0; q < 4; q++) acc[mi][ni][q] = 0.0f;

    uint32_t smbase = (uint32_t)__cvta_generic_to_shared(sm);
    uint32_t xbuf[2] = { smbase + OFF_XH0, smbase + OFF_XH1 };
    uint32_t cbuf[2] = { smbase + OFF_CH0, smbase + OFF_CH1 };

    // ---- issue both chunks via cp.async (double-buffered) ----
    #pragma unroll
    for (int c = 0; c < 2; c++) {
        int k0 = c * 64;
        #pragma unroll
        for (int it = 0; it < 4; it++) {
            int idx = tid + 256 * it;            // 0..1023
            int p = idx >> 3, s = idx & 7;       // row, 16B-slot
            int pc = tile0 + p; if (pc >= N) pc = N - 1;
            CP_ASYNC16(xbuf[c] + (uint32_t)((p * XST + s * 8) * 2),
                       g_xh[xset] + (size_t)pc * DC + k0 + s * 8);
            int pk = p < KC ? p : KC - 1;        // pad rows: dup row 119 (acc unread)
            CP_ASYNC16(cbuf[c] + (uint32_t)((p * XST + s * 8) * 2),
                       g_ch[cset] + pk * DC + k0 + s * 8);
        }
        CP_COMMIT();
    }

    // ldmatrix per-lane selectors
    int arow  = ((lane >> 3) & 1) * 8 + (lane & 7);   // A x4: rows 0-7/8-15, k0/k8
    int acol8 = ((lane >> 4) & 1) * 8;
    int brow  = ((lane >> 4) & 1) * 8 + (lane & 7);   // B x4: n-rows 0-7/8-15
    int bcol8 = ((lane >> 3) & 1) * 8;                //       k0 / k8

    #pragma unroll
    for (int c = 0; c < 2; c++) {
        if (c == 0) { CP_WAIT(1); } else { CP_WAIT(0); }
        __syncthreads();
        uint32_t xh_s = xbuf[c], ch_s = cbuf[c];
        #pragma unroll
        for (int ks = 0; ks < 4; ks++) {
            int kk = ks * 16;
            uint32_t a[2][4];
            #pragma unroll
            for (int mi = 0; mi < 2; mi++) {
                uint32_t aoff = (uint32_t)(((pm + mi * 16 + arow) * XST + kk + acol8) * 2);
                ldsm_x4(a[mi], xh_s + aoff);
            }
            #pragma unroll
            for (int pr = 0; pr < 4; pr++) {      // pairs of ni
                uint32_t boff = (uint32_t)(((nb + pr * 16 + brow) * XST + kk + bcol8) * 2);
                uint32_t bh[4];
                ldsm_x4(bh, ch_s + boff);
                #pragma unroll
                for (int mi = 0; mi < 2; mi++) {
                    mma16816(acc[mi][2 * pr],     a[mi], bh[0], bh[1]);
                    mma16816(acc[mi][2 * pr + 1], a[mi], bh[2], bh[3]);
                }
            }
        }
    }
    __syncthreads();   // all mma done before S overwrites staging buffers

    // ---- write S[p][n] (skip pad cols 120..127: wn==1 && ni==7) ----
    #pragma unroll
    for (int mi = 0; mi < 2; mi++) {
        int p0 = pm + mi * 16 + g;
        #pragma unroll
        for (int ni = 0; ni < 8; ni++) {
            if (wn == 1 && ni == 7) continue;
            int n0 = nb + ni * 8 + 2 * t;
            S[p0 * SROW + n0]           = acc[mi][ni][0];
            S[p0 * SROW + n0 + 1]       = acc[mi][ni][1];
            S[(p0 + 8) * SROW + n0]     = acc[mi][ni][2];
            S[(p0 + 8) * SROW + n0 + 1] = acc[mi][ni][3];
        }
    }
    __syncthreads();

    // ---- head: 2 threads per point, 60 clusters each, shfl_xor combine ----
    int pp = tid >> 1;            // point row 0..127
    int hf = tid & 1;             // cluster half
    int p = tile0 + pp;
    bool valid = p < N;
    const float* Sp = S + pp * SROW + hf * 60;

    if (mode == 0) {
        float best = FLT_MAX;
        int bi = 0;
        #pragma unroll 4
        for (int k = 0; k < 60; k++) {
            float dist = csq_s[hf * 60 + k] - 2.0f * Sp[k];
            if (dist < best) { best = dist; bi = hf * 60 + k; }
        }
        float ob = __shfl_xor_sync(0xffffffffu, best, 1);
        int   oi = __shfl_xor_sync(0xffffffffu, bi, 1);
        float b0 = hf ? ob : best;  int i0 = hf ? oi : bi;   // half-0
        float b1 = hf ? best : ob;  int i1 = hf ? bi : oi;   // half-1
        int fin = (b1 < b0) ? i1 : i0;   // tie -> half-0 (smaller k)
        if (valid && hf == 0) g_labels[cset][p] = fin;
    } else {
        int lab = valid ? g_labels[cset][p] : 0;
        float m = -3.0e38f, ss = 0.0f, lgl = 0.0f;
        #pragma unroll 4
        for (int k = 0; k < 60; k++) {
            int kk = hf * 60 + k;
            float lg = 2.5f * Sp[k];          // / CLD_T = 0.4
            if (kk == lab) lgl = lg;
            float nm = fmaxf(m, lg);
            ss = ss * __expf(m - nm) + __expf(lg - nm);
            m = nm;
        }
        float om   = __shfl_xor_sync(0xffffffffu, m, 1);
        float oss  = __shfl_xor_sync(0xffffffffu, ss, 1);
        float olgl = __shfl_xor_sync(0xffffffffu, lgl, 1);
        float nm = fmaxf(m, om);
        float tss = ss * __expf(m - nm) + oss * __expf(om - nm);
        float tlgl = lgl + olgl;
        float ce = (valid && hf == 0) ? (nm + logf(tss) - tlgl) : 0.0f;
        #pragma unroll
        for (int o = 16; o > 0; o >>= 1) ce += __shfl_down_sync(0xffffffffu, ce, o);
        float* red = (float*)(sm + OFF_RED);
        if ((tid & 31) == 0) red[tid >> 5] = ce;
        __syncthreads();
        if (tid == 0) {
            float tt = red[0] + red[1] + red[2] + red[3] +
                       red[4] + red[5] + red[6] + red[7];
            atomicAdd(&g_acc[aidx], (double)tt);
        }
    }
}

// ================= centroid init / update (+ fp16 convert) =================
__global__ void centroid_kernel(const float* __restrict__ x, int set, int mode) {
    int k = blockIdx.x;
    int d = threadIdx.x;
    float c;
    if (mode == 0) {
        c = x[k * DC + d];
    } else {
        float cnt = g_counts[k];
        if (cnt == 0.0f) cnt = 1.0f;
        c = g_sums[k * DC + d] / cnt;
    }
    g_cent[set][k * DC + d] = c;
    g_ch[set][k * DC + d] = __float2half_rn(c);
    g_sums[k * DC + d] = 0.0f;
    if (d == 0) g_counts[k] = 0.0f;

    float v = c * c;
    #pragma unroll
    for (int o = 16; o > 0; o >>= 1) v += __shfl_down_sync(0xffffffffu, v, o);
    __shared__ float rsm[4];
    if ((d & 31) == 0) rsm[d >> 5] = v;
    __syncthreads();
    if (d == 0) g_csq[set][k] = rsm[0] + rsm[1] + rsm[2] + rsm[3];
}

// ================= scatter reduce (batch-32 MLP, smem atomics) =================
#define RGRID 148
#define PERMAX 2048
#define REDUCE_SMEM ((2 * KC * DC + 128 + PERMAX) * 4)

__global__ __launch_bounds__(256, 1)
void reduce_kernel(const float* __restrict__ x, int set, int N) {
    float* smf = (float*)dyn_smem;
    float* sumA = smf;                         // KC*DC
    float* sumB = smf + KC * DC;               // KC*DC
    float* scnt = smf + 2 * KC * DC;           // 128 (120 used)
    int*   slab = (int*)(smf + 2 * KC * DC + 128);

    int tid = threadIdx.x;
    for (int i = tid; i < 2 * KC * DC; i += 256) smf[i] = 0.0f;
    for (int i = tid; i < 128; i += 256) scnt[i] = 0.0f;

    const int* __restrict__ lab = g_labels[set];
    int G = gridDim.x;
    int per = (N + G - 1) / G;
    int p0 = blockIdx.x * per;
    int cnt = min(N, p0 + per) - p0;
    if (cnt < 0) cnt = 0;

    for (int i = tid; i < cnt; i += 256) slab[i] = lab[p0 + i];
    __syncthreads();

    int half = tid >> 7;       // 0 or 1
    int d = tid & 127;
    float* mysum = half ? sumB : sumA;
    int mid = cnt >> 1;
    int qs = half ? mid : 0;
    int qe = half ? cnt : mid;

    const float* __restrict__ xb = x + (size_t)p0 * DC + d;
    int q = qs;
    for (; q + 32 <= qe; q += 32) {
        float v[32];
        #pragma unroll
        for (int i = 0; i < 32; i++)
            v[i] = __ldg(xb + (size_t)(q + i) * DC);
        int l[32];
        #pragma unroll
        for (int i = 0; i < 32; i++) l[i] = slab[q + i];
        #pragma unroll
        for (int i = 0; i < 32; i++)
            atomicAdd(&mysum[l[i] * DC + d], v[i]);
    }
    for (; q < qe; ++q)
        atomicAdd(&mysum[slab[q] * DC + d], __ldg(xb + (size_t)q * DC));

    // counts (spread smem atomics over staged labels)
    for (int i = tid; i < cnt; i += 256)
        atomicAdd(&scnt[slab[i]], 1.0f);
    __syncthreads();

    for (int i = tid; i < KC * DC; i += 256)
        atomicAdd(&g_sums[i], sumA[i] + sumB[i]);
    for (int i = tid; i < KC; i += 256)
        atomicAdd(&g_counts[i], scnt[i]);
}

__global__ void zero_acc_kernel() {
    if (threadIdx.x < 2) g_acc[threadIdx.x] = 0.0;
}
__global__ void finalize_kernel(float* out, int N) {
    out[0] = (float)((g_acc[0] + g_acc[1]) / (2.0 * (double)N));
}

// ================= launch =================
extern "C" void kernel_launch(void* const* d_in, const int* in_sizes, int n_in,
                              void* d_out, int out_size) {
    const float* f1 = (const float*)d_in[0];
    const float* f2 = (const float*)d_in[1];
    int N = in_sizes[0] / DC;

    cudaFuncSetAttribute(gemm_head_kernel, cudaFuncAttributeMaxDynamicSharedMemorySize, GEMM_SMEM);
    cudaFuncSetAttribute(reduce_kernel, cudaFuncAttributeMaxDynamicSharedMemorySize, REDUCE_SMEM);

    int ggrid = (N + TILE_M - 1) / TILE_M;
    int total4 = N * DC / 4;
    int pgrid = (total4 + 255) / 256;

    preconvert_kernel<<<pgrid, 256>>>(f1, 0, total4);
    preconvert_kernel<<<pgrid, 256>>>(f2, 1, total4);

    for (int s = 0; s < 2; ++s) {
        const float* x = s ? f2 : f1;
        centroid_kernel<<<KC, DC>>>(x, s, 0);
        for (int it = 0; it < 5; ++it) {
            gemm_head_kernel<<<ggrid, 256, GEMM_SMEM>>>(s, s, 0, 0, N);
            reduce_kernel<<<RGRID, 256, REDUCE_SMEM>>>(x, s, N);
            centroid_kernel<<<KC, DC>>>(nullptr, s, 1);
        }
    }
    zero_acc_kernel<<<1, 32>>>();
    gemm_head_kernel<<<ggrid, 256, GEMM_SMEM>>>(0, 1, 1, 0, N);  // X=f1 vs c2/cl2
    gemm_head_kernel<<<ggrid, 256, GEMM_SMEM>>>(1, 0, 1, 1, N);  // X=f2 vs c1/cl1
    finalize_kernel<<<1, 1>>>((float*)d_out, N);
}

// round 17
// speedup vs baseline: 1.0120x; 1.0120x over previous
#include <cuda_runtime.h>
#include <cuda_fp16.h>
#include <cstdint>
#include <cfloat>

#define KC 120
#define DC 128
#define NMAX 262144
#define TILE_M 128
#define SROW 121          // S row stride (floats), odd => conflict-free
#define XST 72            // f16 row stride (64 + 8 pad) => conflict-free ldmatrix

typedef unsigned long long u64;

// ---------------- device scratch ----------------
__device__ float  g_cent[2][KC * DC];
__device__ float  g_csq[2][KC];
__device__ float  g_sums[KC * DC];
__device__ float  g_counts[KC];
__device__ int    g_labels[2][NMAX];
__device__ double g_acc[2];
// X and C in plain fp16 (X once per replay; C per iteration)
__device__ __half g_xh[2][NMAX * DC];
__device__ __half g_ch[2][KC * DC];

// single dynamic-smem symbol shared by all kernels (cast locally)
extern __shared__ char dyn_smem[];

// ---------------- smem layout (gemm kernel) ----------------
#define OFF_CSQ 0                       // 128 floats
#define OFF_RED 512                     // 8 floats
#define OFF_XH0 1024                    // 128 x 72 f16 = 18432 B
#define OFF_CH0 (1024 + 18432)
#define OFF_XH1 (1024 + 2 * 18432)
#define OFF_CH1 (1024 + 3 * 18432)
#define OFF_S   1024                    // epilogue S overlaps staging
#define GEMM_SMEM (1024 + 4 * 18432)    // 74752 B

// m16n8k16 f16 mma, fp32 accumulate
__device__ __forceinline__ void mma16816(float* c, const uint32_t* a,
                                         uint32_t b0, uint32_t b1) {
    asm volatile(
        "mma.sync.aligned.m16n8k16.row.col.f32.f16.f16.f32 "
        "{%0,%1,%2,%3}, {%4,%5,%6,%7}, {%8,%9}, {%0,%1,%2,%3};"
        : "+f"(c[0]), "+f"(c[1]), "+f"(c[2]), "+f"(c[3])
        : "r"(a[0]), "r"(a[1]), "r"(a[2]), "r"(a[3]), "r"(b0), "r"(b1));
}
__device__ __forceinline__ void ldsm_x4(uint32_t* r, uint32_t addr) {
    asm volatile("ldmatrix.sync.aligned.m8n8.x4.shared.b16 {%0,%1,%2,%3}, [%4];"
        : "=r"(r[0]), "=r"(r[1]), "=r"(r[2]), "=r"(r[3]) : "r"(addr));
}
#define CP_ASYNC16(dst, src) \
    asm volatile("cp.async.cg.shared.global [%0], [%1], 16;" :: "r"(dst), "l"(src))
#define CP_COMMIT() asm volatile("cp.async.commit_group;")
#define CP_WAIT(n)  asm volatile("cp.async.wait_group %0;" :: "n"(n))

// ================= one-time fp16 conversion of X =================
__global__ __launch_bounds__(256)
void preconvert_kernel(const float* __restrict__ x, int set, int total4) {
    int idx = blockIdx.x * 256 + threadIdx.x;    // float4 index
    if (idx >= total4) return;
    float4 v = ((const float4*)x)[idx];
    __half2* dh = (__half2*)(g_xh[set]) + idx * 2;
    dh[0] = __halves2half2(__float2half_rn(v.x), __float2half_rn(v.y));
    dh[1] = __halves2half2(__float2half_rn(v.z), __float2half_rn(v.w));
}

// ================= tensor-core GEMM + head (pure fp16, fp32 acc) =================
__global__ __launch_bounds__(256, 2)
void gemm_head_kernel(int xset, int cset, int mode, int aidx, int N) {
    char* sm = dyn_smem;
    float*  csq_s = (float*)(sm + OFF_CSQ);
    float*  S  = (float*)(sm + OFF_S);

    int tid = threadIdx.x;
    int lane = tid & 31, g = lane >> 2, t = lane & 3;
    int warp = tid >> 5;
    int wm = warp >> 1;
    int wn = warp & 1;
    int pm = wm * 32;
    int nb = wn * 64;

    if (mode == 0 && tid < KC) csq_s[tid] = g_csq[cset][tid];

    int tile0 = blockIdx.x * TILE_M;

    float acc[2][8][4];
    #pragma unroll
    for (int mi = 0; mi < 2; mi++)
        #pragma unroll
        for (int ni = 0; ni < 8; ni++)
            #pragma unroll
            for (int q = 0; q < 4; q++) acc[mi][ni][q] = 0.0f;

    uint32_t smbase = (uint32_t)__cvta_generic_to_shared(sm);
    uint32_t xbuf[2] = { smbase + OFF_XH0, smbase + OFF_XH1 };
    uint32_t cbuf[2] = { smbase + OFF_CH0, smbase + OFF_CH1 };

    #pragma unroll
    for (int c = 0; c < 2; c++) {
        int k0 = c * 64;
        #pragma unroll
        for (int it = 0; it < 4; it++) {
            int idx = tid + 256 * it;
            int p = idx >> 3, s = idx & 7;
            int pc = tile0 + p; if (pc >= N) pc = N - 1;
            CP_ASYNC16(xbuf[c] + (uint32_t)((p * XST + s * 8) * 2),
                       g_xh[xset] + (size_t)pc * DC + k0 + s * 8);
            int pk = p < KC ? p : KC - 1;
            CP_ASYNC16(cbuf[c] + (uint32_t)((p * XST + s * 8) * 2),
                       g_ch[cset] + pk * DC + k0 + s * 8);
        }
        CP_COMMIT();
    }

    int arow  = ((lane >> 3) & 1) * 8 + (lane & 7);
    int acol8 = ((lane >> 4) & 1) * 8;
    int brow  = ((lane >> 4) & 1) * 8 + (lane & 7);
    int bcol8 = ((lane >> 3) & 1) * 8;

    #pragma unroll
    for (int c = 0; c < 2; c++) {
        if (c == 0) { CP_WAIT(1); } else { CP_WAIT(0); }
        __syncthreads();
        uint32_t xh_s = xbuf[c], ch_s = cbuf[c];
        #pragma unroll
        for (int ks = 0; ks < 4; ks++) {
            int kk = ks * 16;
            uint32_t a[2][4];
            #pragma unroll
            for (int mi = 0; mi < 2; mi++) {
                uint32_t aoff = (uint32_t)(((pm + mi * 16 + arow) * XST + kk + acol8) * 2);
                ldsm_x4(a[mi], xh_s + aoff);
            }
            #pragma unroll
            for (int pr = 0; pr < 4; pr++) {
                uint32_t boff = (uint32_t)(((nb + pr * 16 + brow) * XST + kk + bcol8) * 2);
                uint32_t bh[4];
                ldsm_x4(bh, ch_s + boff);
                #pragma unroll
                for (int mi = 0; mi < 2; mi++) {
                    mma16816(acc[mi][2 * pr],     a[mi], bh[0], bh[1]);
                    mma16816(acc[mi][2 * pr + 1], a[mi], bh[2], bh[3]);
                }
            }
        }
    }
    __syncthreads();

    #pragma unroll
    for (int mi = 0; mi < 2; mi++) {
        int p0 = pm + mi * 16 + g;
        #pragma unroll
        for (int ni = 0; ni < 8; ni++) {
            if (wn == 1 && ni == 7) continue;
            int n0 = nb + ni * 8 + 2 * t;
            S[p0 * SROW + n0]           = acc[mi][ni][0];
            S[p0 * SROW + n0 + 1]       = acc[mi][ni][1];
            S[(p0 + 8) * SROW + n0]     = acc[mi][ni][2];
            S[(p0 + 8) * SROW + n0 + 1] = acc[mi][ni][3];
        }
    }
    __syncthreads();

    // ---- head: 2 threads per point, 60 clusters each, shfl_xor combine ----
    int pp = tid >> 1;
    int hf = tid & 1;
    int p = tile0 + pp;
    bool valid = p < N;
    const float* Sp = S + pp * SROW + hf * 60;

    if (mode == 0) {
        float best = FLT_MAX;
        int bi = 0;
        #pragma unroll 4
        for (int k = 0; k < 60; k++) {
            float dist = csq_s[hf * 60 + k] - 2.0f * Sp[k];
            if (dist < best) { best = dist; bi = hf * 60 + k; }
        }
        float ob = __shfl_xor_sync(0xffffffffu, best, 1);
        int   oi = __shfl_xor_sync(0xffffffffu, bi, 1);
        float b0 = hf ? ob : best;  int i0 = hf ? oi : bi;
        float b1 = hf ? best : ob;  int i1 = hf ? bi : oi;
        int fin = (b1 < b0) ? i1 : i0;   // tie -> half-0 (smaller k)
        if (valid && hf == 0) g_labels[cset][p] = fin;
    } else {
        int lab = valid ? g_labels[cset][p] : 0;
        float m = -3.0e38f, ss = 0.0f, lgl = 0.0f;
        #pragma unroll 4
        for (int k = 0; k < 60; k++) {
            int kk = hf * 60 + k;
            float lg = 2.5f * Sp[k];
            if (kk == lab) lgl = lg;
            float nm = fmaxf(m, lg);
            ss = ss * __expf(m - nm) + __expf(lg - nm);
            m = nm;
        }
        float om   = __shfl_xor_sync(0xffffffffu, m, 1);
        float oss  = __shfl_xor_sync(0xffffffffu, ss, 1);
        float olgl = __shfl_xor_sync(0xffffffffu, lgl, 1);
        float nm = fmaxf(m, om);
        float tss = ss * __expf(m - nm) + oss * __expf(om - nm);
        float tlgl = lgl + olgl;
        float ce = (valid && hf == 0) ? (nm + logf(tss) - tlgl) : 0.0f;
        #pragma unroll
        for (int o = 16; o > 0; o >>= 1) ce += __shfl_down_sync(0xffffffffu, ce, o);
        float* red = (float*)(sm + OFF_RED);
        if ((tid & 31) == 0) red[tid >> 5] = ce;
        __syncthreads();
        if (tid == 0) {
            float tt = red[0] + red[1] + red[2] + red[3] +
                       red[4] + red[5] + red[6] + red[7];
            atomicAdd(&g_acc[aidx], (double)tt);
        }
    }
}

// ================= centroid init / update (+ fp16 convert) =================
__global__ void centroid_kernel(const float* __restrict__ x, int set, int mode) {
    int k = blockIdx.x;
    int d = threadIdx.x;
    float c;
    if (mode == 0) {
        c = x[k * DC + d];
    } else {
        float cnt = g_counts[k];
        if (cnt == 0.0f) cnt = 1.0f;
        c = g_sums[k * DC + d] / cnt;
    }
    g_cent[set][k * DC + d] = c;
    g_ch[set][k * DC + d] = __float2half_rn(c);
    g_sums[k * DC + d] = 0.0f;
    if (d == 0) g_counts[k] = 0.0f;

    float v = c * c;
    #pragma unroll
    for (int o = 16; o > 0; o >>= 1) v += __shfl_down_sync(0xffffffffu, v, o);
    __shared__ float rsm[4];
    if ((d & 31) == 0) rsm[d >> 5] = v;
    __syncthreads();
    if (d == 0) g_csq[set][k] = rsm[0] + rsm[1] + rsm[2] + rsm[3];
}

// ================= scatter reduce v2: cp.async-staged tiles =================
// smem floats: sumA[15360] sumB[15360] scnt[128] slab[1792(int)] xt[2][8192]
#define RGRID 148
#define RTILE 64
#define RSL_SUMB 15360
#define RSL_CNT  30720
#define RSL_LAB  30848
#define RSL_XT   32640
#define REDUCE_SMEM ((RSL_XT + 2 * RTILE * DC) * 4)   // 196096 B

__global__ __launch_bounds__(256, 1)
void reduce_kernel(const float* __restrict__ x, int set, int N) {
    float* smf = (float*)dyn_smem;
    float* sumA = smf;
    float* sumB = smf + RSL_SUMB;
    float* scnt = smf + RSL_CNT;
    int*   slab = (int*)(smf + RSL_LAB);
    float* xt[2] = { smf + RSL_XT, smf + RSL_XT + RTILE * DC };

    int tid = threadIdx.x;
    for (int i = tid; i < 2 * KC * DC; i += 256) smf[i] = 0.0f;
    for (int i = tid; i < 128; i += 256) scnt[i] = 0.0f;

    const int* __restrict__ lab = g_labels[set];
    int G = gridDim.x;
    int per = (N + G - 1) / G;
    int p0 = blockIdx.x * per;
    int cnt = min(N, p0 + per) - p0;
    if (cnt < 0) cnt = 0;

    for (int i = tid; i < cnt; i += 256) slab[i] = lab[p0 + i];
    __syncthreads();

    int half = tid >> 7;
    int d = tid & 127;
    float* mysum = half ? sumB : sumA;

    uint32_t xt_s[2] = { (uint32_t)__cvta_generic_to_shared(xt[0]),
                         (uint32_t)__cvta_generic_to_shared(xt[1]) };
    int ntiles = (cnt + RTILE - 1) / RTILE;

    // issue tile 0
    if (ntiles > 0) {
        #pragma unroll
        for (int it = 0; it < 8; it++) {
            int idx = tid + 256 * it;              // 0..2047 16B-slots
            int row = idx >> 5, s = idx & 31;
            int pc = p0 + row; if (pc >= N) pc = N - 1;
            CP_ASYNC16(xt_s[0] + (uint32_t)((row * DC + s * 4) * 4),
                       x + (size_t)pc * DC + s * 4);
        }
        CP_COMMIT();
    }

    for (int t = 0; t < ntiles; t++) {
        if (t + 1 < ntiles) {
            int qb = (t + 1) * RTILE;
            #pragma unroll
            for (int it = 0; it < 8; it++) {
                int idx = tid + 256 * it;
                int row = idx >> 5, s = idx & 31;
                int pc = p0 + qb + row; if (pc >= N) pc = N - 1;
                CP_ASYNC16(xt_s[(t + 1) & 1] + (uint32_t)((row * DC + s * 4) * 4),
                           x + (size_t)pc * DC + s * 4);
            }
            CP_COMMIT();
            CP_WAIT(1);
        } else {
            CP_WAIT(0);
        }
        __syncthreads();

        const float* xb = xt[t & 1] + half * 32 * DC + d;
        int qb = t * RTILE + half * 32;
        #pragma unroll 8
        for (int i = 0; i < 32; i++) {
            int q = qb + i;
            if (q < cnt)
                atomicAdd(&mysum[slab[q] * DC + d], xb[i * DC]);
        }
        __syncthreads();
    }

    // counts
    for (int i = tid; i < cnt; i += 256)
        atomicAdd(&scnt[slab[i]], 1.0f);
    __syncthreads();

    for (int i = tid; i < KC * DC; i += 256)
        atomicAdd(&g_sums[i], sumA[i] + sumB[i]);
    for (int i = tid; i < KC; i += 256)
        atomicAdd(&g_counts[i], scnt[i]);
}

__global__ void zero_acc_kernel() {
    if (threadIdx.x < 2) g_acc[threadIdx.x] = 0.0;
}
__global__ void finalize_kernel(float* out, int N) {
    out[0] = (float)((g_acc[0] + g_acc[1]) / (2.0 * (double)N));
}

// ================= launch =================
extern "C" void kernel_launch(void* const* d_in, const int* in_sizes, int n_in,
                              void* d_out, int out_size) {
    const float* f1 = (const float*)d_in[0];
    const float* f2 = (const float*)d_in[1];
    int N = in_sizes[0] / DC;

    cudaFuncSetAttribute(gemm_head_kernel, cudaFuncAttributeMaxDynamicSharedMemorySize, GEMM_SMEM);
    cudaFuncSetAttribute(reduce_kernel, cudaFuncAttributeMaxDynamicSharedMemorySize, REDUCE_SMEM);

    int ggrid = (N + TILE_M - 1) / TILE_M;
    int total4 = N * DC / 4;
    int pgrid = (total4 + 255) / 256;

    preconvert_kernel<<<pgrid, 256>>>(f1, 0, total4);
    preconvert_kernel<<<pgrid, 256>>>(f2, 1, total4);

    for (int s = 0; s < 2; ++s) {
        const float* x = s ? f2 : f1;
        centroid_kernel<<<KC, DC>>>(x, s, 0);
        for (int it = 0; it < 5; ++it) {
            gemm_head_kernel<<<ggrid, 256, GEMM_SMEM>>>(s, s, 0, 0, N);
            reduce_kernel<<<RGRID, 256, REDUCE_SMEM>>>(x, s, N);
            centroid_kernel<<<KC, DC>>>(nullptr, s, 1);
        }
    }
    zero_acc_kernel<<<1, 32>>>();
    gemm_head_kernel<<<ggrid, 256, GEMM_SMEM>>>(0, 1, 1, 0, N);  // X=f1 vs c2/cl2
    gemm_head_kernel<<<ggrid, 256, GEMM_SMEM>>>(1, 0, 1, 1, N);  // X=f2 vs c1/cl1
    finalize_kernel<<<1, 1>>>((float*)d_out, N);
}